// round 1
// baseline (speedup 1.0000x reference)
#include <cuda_runtime.h>
#include <math.h>

// Problem constants (fixed for this dataset)
#define N_NODES 50000
#define E_EDGES 1600000
#define EP      (E_EDGES + N_NODES)   // edges + self loops
#define HC      32                    // H*C
#define G_GRAPHS 512

// ---------------- scratch (static __device__, no allocation) ----------------
__device__ int   g_outdeg[N_NODES];
__device__ int   g_indeg [N_NODES];
__device__ int   g_rowptr[N_NODES + 1];
__device__ int   g_woff  [N_NODES];
__device__ int   g_col   [EP];
__device__ float g_xl [N_NODES * HC];
__device__ float g_xr [N_NODES * HC];
__device__ float g_h  [N_NODES * HC];
__device__ float g_sums[G_GRAPHS * HC];
__device__ float g_cnt [G_GRAPHS];

// ---------------- kernels ----------------
__global__ void zero_kernel() {
    int i = blockIdx.x * blockDim.x + threadIdx.x;
    if (i < N_NODES) { g_outdeg[i] = 0; g_indeg[i] = 0; }
    if (i < G_GRAPHS * HC) g_sums[i] = 0.f;
    if (i < G_GRAPHS) g_cnt[i] = 0.f;
}

__global__ void degree_kernel(const int* __restrict__ ei) {
    int e = blockIdx.x * blockDim.x + threadIdx.x;
    if (e >= E_EDGES) return;
    int s = ei[e];
    int d = ei[E_EDGES + e];
    atomicAdd(&g_outdeg[s], 1);
    atomicAdd(&g_indeg[d], 1);
}

// Exclusive scan of (indeg[i] + 1) -> row_ptr, also primes write offsets.
// One block of 1024 threads, two passes over chunks.
__global__ void scan_kernel() {
    __shared__ int part[1024];
    const int t = threadIdx.x;
    const int per = (N_NODES + 1023) / 1024;   // 49
    int lo = t * per;
    int hi = min(lo + per, N_NODES);
    int s = 0;
    for (int i = lo; i < hi; i++) s += g_indeg[i] + 1;
    part[t] = s;
    __syncthreads();
    for (int off = 1; off < 1024; off <<= 1) {
        int v = (t >= off) ? part[t - off] : 0;
        __syncthreads();
        part[t] += v;
        __syncthreads();
    }
    int run = part[t] - s;   // exclusive prefix
    for (int i = lo; i < hi; i++) {
        g_rowptr[i] = run;
        g_woff[i]   = run;
        run += g_indeg[i] + 1;
    }
    if (t == 1023) g_rowptr[N_NODES] = part[1023];
}

__global__ void scatter_kernel(const int* __restrict__ ei) {
    int e = blockIdx.x * blockDim.x + threadIdx.x;
    if (e >= EP) return;
    int s, d;
    if (e < E_EDGES) { s = ei[e]; d = ei[E_EDGES + e]; }
    else             { s = e - E_EDGES; d = s; }       // self loop
    int pos = atomicAdd(&g_woff[d], 1);
    g_col[pos] = s;
}

// x0 = [1, deg, rand]; xl = x0 @ W1l^T + b1l ; xr = x0 @ W1r^T + b1r
// warp per node, lane = output channel
__global__ void feat_lin1_kernel(const float* __restrict__ rand_feat,
                                 const float* __restrict__ Wl, const float* __restrict__ bl,
                                 const float* __restrict__ Wr, const float* __restrict__ br) {
    int idx = blockIdx.x * blockDim.x + threadIdx.x;   // = node*32 + lane
    int node = idx >> 5, lane = idx & 31;
    if (node >= N_NODES) return;
    float x1 = (float)(g_outdeg[node] + g_indeg[node]);
    float x2 = rand_feat[node];
    float l = Wl[lane * 3 + 0] + Wl[lane * 3 + 1] * x1 + Wl[lane * 3 + 2] * x2 + bl[lane];
    float r = Wr[lane * 3 + 0] + Wr[lane * 3 + 1] * x1 + Wr[lane * 3 + 2] * x2 + br[lane];
    g_xl[idx] = l;
    g_xr[idx] = r;
}

// GATv2 conv: warp per destination node, lane = channel (head = lane/16).
// Online (streaming) segment softmax -> single pass over incoming edges.
// Writes ELU(out + bias) into g_h.
__global__ void conv_kernel(const float* __restrict__ att,
                            const float* __restrict__ bias) {
    int idx = blockIdx.x * blockDim.x + threadIdx.x;   // = node*32 + lane
    int node = idx >> 5, lane = idx & 31;
    if (node >= N_NODES) return;
    float xr_l  = g_xr[idx];
    float att_l = att[lane];                 // att[h*16+c] == att[lane]
    int beg = g_rowptr[node];
    int end = g_rowptr[node + 1];
    float mmax = -1e30f, denom = 0.f, acc = 0.f;
    for (int e = beg; e < end; e++) {
        int s  = g_col[e];
        float v = g_xl[s * HC + lane];       // coalesced 128B gather (L2 hit)
        float m = v + xr_l;
        float lr = m > 0.f ? m : 0.2f * m;   // LeakyReLU(0.2)
        float p = lr * att_l;
        // half-warp (16 lane) sum -> per-head attention score
        p += __shfl_xor_sync(0xffffffffu, p, 1);
        p += __shfl_xor_sync(0xffffffffu, p, 2);
        p += __shfl_xor_sync(0xffffffffu, p, 4);
        p += __shfl_xor_sync(0xffffffffu, p, 8);
        // online softmax update
        float nm   = fmaxf(mmax, p);
        float corr = __expf(mmax - nm);
        float w    = __expf(p - nm);
        denom = denom * corr + w;
        acc   = acc * corr + w * v;
        mmax  = nm;
    }
    float o = acc / (denom + 1e-16f) + bias[lane];
    g_h[idx] = o > 0.f ? o : (__expf(o) - 1.f);   // ELU
}

// xl/xr = h @ W^T + b, 32->32, warp per node, W cached in padded shared
__global__ void lin2_kernel(const float* __restrict__ Wl, const float* __restrict__ bl,
                            const float* __restrict__ Wr, const float* __restrict__ br) {
    __shared__ float sWl[32 * 33];
    __shared__ float sWr[32 * 33];
    int tid = threadIdx.x;
    for (int i = tid; i < 1024; i += blockDim.x) {
        int r = i >> 5, c = i & 31;
        sWl[r * 33 + c] = Wl[i];
        sWr[r * 33 + c] = Wr[i];
    }
    __syncthreads();
    int idx = blockIdx.x * blockDim.x + tid;
    int node = idx >> 5, lane = idx & 31;
    if (node >= N_NODES) return;
    float hv = g_h[idx];
    float aL = bl[lane], aR = br[lane];
#pragma unroll
    for (int k = 0; k < 32; k++) {
        float hk = __shfl_sync(0xffffffffu, hv, k);
        aL += hk * sWl[lane * 33 + k];
        aR += hk * sWr[lane * 33 + k];
    }
    g_xl[idx] = aL;
    g_xr[idx] = aR;
}

__global__ void pool_kernel(const int* __restrict__ batch) {
    int idx = blockIdx.x * blockDim.x + threadIdx.x;
    if (idx >= N_NODES * HC) return;
    int node = idx >> 5, c = idx & 31;
    int g = batch[node];
    atomicAdd(&g_sums[g * HC + c], g_h[idx]);
    if (c == 0) atomicAdd(&g_cnt[g], 1.f);
}

// warp per graph: mean pool -> fc(32->2) -> log_softmax
__global__ void head_kernel(const float* __restrict__ Wfc, const float* __restrict__ bfc,
                            float* __restrict__ out) {
    int idx = blockIdx.x * blockDim.x + threadIdx.x;
    int g = idx >> 5, lane = idx & 31;
    if (g >= G_GRAPHS) return;
    float cnt = fmaxf(g_cnt[g], 1.f);
    float pooled = g_sums[g * HC + lane] / cnt;
    float p0 = pooled * Wfc[lane];
    float p1 = pooled * Wfc[HC + lane];
#pragma unroll
    for (int off = 16; off; off >>= 1) {
        p0 += __shfl_xor_sync(0xffffffffu, p0, off);
        p1 += __shfl_xor_sync(0xffffffffu, p1, off);
    }
    if (lane == 0) {
        float l0 = p0 + bfc[0];
        float l1 = p1 + bfc[1];
        float mx = fmaxf(l0, l1);
        float lse = mx + logf(expf(l0 - mx) + expf(l1 - mx));
        out[g * 2 + 0] = l0 - lse;
        out[g * 2 + 1] = l1 - lse;
    }
}

// ---------------- launch ----------------
extern "C" void kernel_launch(void* const* d_in, const int* in_sizes, int n_in,
                              void* d_out, int out_size) {
    const int*   ei        = (const int*)  d_in[0];
    const int*   batch     = (const int*)  d_in[1];
    const float* rand_feat = (const float*)d_in[2];
    const float* W1l  = (const float*)d_in[3];
    const float* b1l  = (const float*)d_in[4];
    const float* W1r  = (const float*)d_in[5];
    const float* b1r  = (const float*)d_in[6];
    const float* att1 = (const float*)d_in[7];
    const float* bias1= (const float*)d_in[8];
    const float* W2l  = (const float*)d_in[9];
    const float* b2l  = (const float*)d_in[10];
    const float* W2r  = (const float*)d_in[11];
    const float* b2r  = (const float*)d_in[12];
    const float* att2 = (const float*)d_in[13];
    const float* bias2= (const float*)d_in[14];
    const float* Wfc  = (const float*)d_in[15];
    const float* bfc  = (const float*)d_in[16];
    float* out = (float*)d_out;

    zero_kernel   <<<(N_NODES + 255) / 256, 256>>>();
    degree_kernel <<<(E_EDGES + 255) / 256, 256>>>(ei);
    scan_kernel   <<<1, 1024>>>();
    scatter_kernel<<<(EP + 255) / 256, 256>>>(ei);

    feat_lin1_kernel<<<(N_NODES * HC + 255) / 256, 256>>>(rand_feat, W1l, b1l, W1r, b1r);
    conv_kernel     <<<(N_NODES * HC + 255) / 256, 256>>>(att1, bias1);
    lin2_kernel     <<<(N_NODES * HC + 255) / 256, 256>>>(W2l, b2l, W2r, b2r);
    conv_kernel     <<<(N_NODES * HC + 255) / 256, 256>>>(att2, bias2);

    pool_kernel<<<(N_NODES * HC + 255) / 256, 256>>>(batch);
    head_kernel<<<(G_GRAPHS * 32 + 255) / 256, 256>>>(Wfc, bfc, out);
}

// round 3
// speedup vs baseline: 1.1723x; 1.1723x over previous
#include <cuda_runtime.h>
#include <math.h>

#define N_NODES 50000
#define E_EDGES 1600000
#define HC      32
#define G_GRAPHS 512

// ---------------- static scratch ----------------
__device__ int   g_outdeg[N_NODES];
__device__ int   g_indeg [N_NODES];
__device__ int   g_rowptr[N_NODES + 1];
__device__ int   g_woff  [N_NODES];
__device__ int   g_col   [E_EDGES];
__device__ float g_xl [N_NODES * HC];
__device__ float g_xr [N_NODES * HC];
__device__ float g_xl2[N_NODES * HC];
__device__ float g_xr2[N_NODES * HC];
__device__ float g_sums[G_GRAPHS * HC];

// ---------------- helpers ----------------
__device__ __forceinline__ float hsum16(float p) {
    p += __shfl_xor_sync(0xffffffffu, p, 1);
    p += __shfl_xor_sync(0xffffffffu, p, 2);
    p += __shfl_xor_sync(0xffffffffu, p, 4);
    p += __shfl_xor_sync(0xffffffffu, p, 8);
    return p;
}

// ---------------- kernels ----------------
__global__ void zero_kernel() {
    int i = blockIdx.x * blockDim.x + threadIdx.x;
    if (i < N_NODES) { g_outdeg[i] = 0; g_indeg[i] = 0; }
    if (i < G_GRAPHS * HC) g_sums[i] = 0.f;
}

// 4 edges per thread, int4 loads, non-returning atomics
__global__ void degree_kernel(const int* __restrict__ ei) {
    int e0 = (blockIdx.x * blockDim.x + threadIdx.x) * 4;
    if (e0 >= E_EDGES) return;
    int4 s = *(const int4*)(ei + e0);
    int4 d = *(const int4*)(ei + E_EDGES + e0);
    atomicAdd(&g_outdeg[s.x], 1); atomicAdd(&g_outdeg[s.y], 1);
    atomicAdd(&g_outdeg[s.z], 1); atomicAdd(&g_outdeg[s.w], 1);
    atomicAdd(&g_indeg[d.x], 1);  atomicAdd(&g_indeg[d.y], 1);
    atomicAdd(&g_indeg[d.z], 1);  atomicAdd(&g_indeg[d.w], 1);
}

// exclusive scan of indeg -> rowptr (and primes woff). Single 1024-thread block.
__global__ void scan_kernel() {
    __shared__ int part[1024];
    const int t = threadIdx.x;
    const int per = (N_NODES + 1023) / 1024;
    int lo = t * per;
    int hi = min(lo + per, N_NODES);
    int s = 0;
    for (int i = lo; i < hi; i++) s += g_indeg[i];
    part[t] = s;
    __syncthreads();
    for (int off = 1; off < 1024; off <<= 1) {
        int v = (t >= off) ? part[t - off] : 0;
        __syncthreads();
        part[t] += v;
        __syncthreads();
    }
    int run = part[t] - s;
    for (int i = lo; i < hi; i++) {
        g_rowptr[i] = run;
        g_woff[i]   = run;
        run += g_indeg[i];
    }
    if (t == 1023) g_rowptr[N_NODES] = part[1023];
}

// 4 edges per thread: 4 independent atomic returns in flight
__global__ void scatter_kernel(const int* __restrict__ ei) {
    int e0 = (blockIdx.x * blockDim.x + threadIdx.x) * 4;
    if (e0 >= E_EDGES) return;
    int4 s = *(const int4*)(ei + e0);
    int4 d = *(const int4*)(ei + E_EDGES + e0);
    int p0 = atomicAdd(&g_woff[d.x], 1);
    int p1 = atomicAdd(&g_woff[d.y], 1);
    int p2 = atomicAdd(&g_woff[d.z], 1);
    int p3 = atomicAdd(&g_woff[d.w], 1);
    g_col[p0] = s.x; g_col[p1] = s.y; g_col[p2] = s.z; g_col[p3] = s.w;
}

// x0 = [1, deg, rand]; xl/xr = x0 @ W^T + b. warp per node, lane = out channel
__global__ void feat_lin1_kernel(const float* __restrict__ rand_feat,
                                 const float* __restrict__ Wl, const float* __restrict__ bl,
                                 const float* __restrict__ Wr, const float* __restrict__ br) {
    int idx = blockIdx.x * blockDim.x + threadIdx.x;
    int node = idx >> 5, lane = idx & 31;
    if (node >= N_NODES) return;
    float x1 = (float)(g_outdeg[node] + g_indeg[node]);
    float x2 = rand_feat[node];
    g_xl[idx] = Wl[lane * 3 + 0] + Wl[lane * 3 + 1] * x1 + Wl[lane * 3 + 2] * x2 + bl[lane];
    g_xr[idx] = Wr[lane * 3 + 0] + Wr[lane * 3 + 1] * x1 + Wr[lane * 3 + 2] * x2 + br[lane];
}

// GATv2 conv, warp per destination, lane = channel (head = lane/16).
// Softmax baseline = self-loop score (mathematically identical; scores ~N(0,0.5^2), no overflow).
// MODE 0: reads g_xl/g_xr, epilogue = fused 32->32 x2 linear -> g_xl2/g_xr2.
// MODE 1: reads g_xl2/g_xr2, epilogue = fused mean-pool atomicAdd into g_sums.
// NOTE: all __device__ globals referenced from device code only (never passed from host).
template<int MODE>
__global__ void conv_kernel(const float* __restrict__ att, const float* __restrict__ bias,
                            const float* __restrict__ Wl, const float* __restrict__ bl,
                            const float* __restrict__ Wr, const float* __restrict__ br,
                            const int* __restrict__ batch) {
    const float* __restrict__ xl = (MODE == 0) ? g_xl : g_xl2;
    const float* __restrict__ xr = (MODE == 0) ? g_xr : g_xr2;

    __shared__ float sWl[32 * 33];
    __shared__ float sWr[32 * 33];
    if (MODE == 0) {
        for (int i = threadIdx.x; i < 1024; i += blockDim.x) {
            int r = i >> 5, c = i & 31;
            sWl[r * 33 + c] = Wl[i];
            sWr[r * 33 + c] = Wr[i];
        }
        __syncthreads();
    }
    int idx = blockIdx.x * blockDim.x + threadIdx.x;
    int node = idx >> 5, lane = idx & 31;
    if (node >= N_NODES) return;

    const float xr_l  = xr[idx];
    const float att_l = att[lane];

    // self loop (coalesced own-row load, not in CSR)
    float vs = xl[idx];
    float ms = vs + xr_l;
    float pself = hsum16(fmaxf(ms, 0.2f * ms) * att_l);

    float denom = 1.f;   // exp(pself - pself)
    float acc   = vs;

    int beg = g_rowptr[node];
    int end = g_rowptr[node + 1];
    int e   = beg;
    int e4  = beg + ((end - beg) & ~3);
    for (; e < e4; e += 4) {
        int s0 = __ldg(g_col + e + 0);
        int s1 = __ldg(g_col + e + 1);
        int s2 = __ldg(g_col + e + 2);
        int s3 = __ldg(g_col + e + 3);
        float v0 = xl[s0 * HC + lane];
        float v1 = xl[s1 * HC + lane];
        float v2 = xl[s2 * HC + lane];
        float v3 = xl[s3 * HC + lane];
        float m0 = v0 + xr_l, m1 = v1 + xr_l, m2 = v2 + xr_l, m3 = v3 + xr_l;
        float p0 = hsum16(fmaxf(m0, 0.2f * m0) * att_l);
        float p1 = hsum16(fmaxf(m1, 0.2f * m1) * att_l);
        float p2 = hsum16(fmaxf(m2, 0.2f * m2) * att_l);
        float p3 = hsum16(fmaxf(m3, 0.2f * m3) * att_l);
        float w0 = __expf(p0 - pself);
        float w1 = __expf(p1 - pself);
        float w2 = __expf(p2 - pself);
        float w3 = __expf(p3 - pself);
        denom += (w0 + w1) + (w2 + w3);
        acc = fmaf(w0, v0, acc);
        acc = fmaf(w1, v1, acc);
        acc = fmaf(w2, v2, acc);
        acc = fmaf(w3, v3, acc);
    }
    for (; e < end; e++) {
        int s = __ldg(g_col + e);
        float v = xl[s * HC + lane];
        float m = v + xr_l;
        float p = hsum16(fmaxf(m, 0.2f * m) * att_l);
        float w = __expf(p - pself);
        denom += w;
        acc = fmaf(w, v, acc);
    }

    float o = acc / (denom + 1e-16f) + bias[lane];
    o = o > 0.f ? o : (__expf(o) - 1.f);   // ELU

    if (MODE == 0) {
        // fused lin2: xl2/xr2 = h @ W^T + b via shuffle broadcast
        float aL = bl[lane], aR = br[lane];
#pragma unroll
        for (int k = 0; k < 32; k++) {
            float hk = __shfl_sync(0xffffffffu, o, k);
            aL = fmaf(hk, sWl[lane * 33 + k], aL);
            aR = fmaf(hk, sWr[lane * 33 + k], aR);
        }
        g_xl2[idx] = aL;
        g_xr2[idx] = aR;
    } else {
        // fused mean-pool accumulation
        int g = batch[node];
        atomicAdd(&g_sums[g * HC + lane], o);
    }
}

__device__ __forceinline__ int lbound(const int* __restrict__ a, int key) {
    int lo = 0, hi = N_NODES;
    while (lo < hi) {
        int mid = (lo + hi) >> 1;
        if (a[mid] < key) lo = mid + 1; else hi = mid;
    }
    return lo;
}

// one warp per graph: counts via binary search on sorted batch, mean pool, fc, log_softmax
__global__ void head_kernel(const int* __restrict__ batch,
                            const float* __restrict__ Wfc, const float* __restrict__ bfc,
                            float* __restrict__ out) {
    int g = blockIdx.x;
    int lane = threadIdx.x;
    int lo = lbound(batch, g);
    int hi = lbound(batch, g + 1);
    float cnt = fmaxf((float)(hi - lo), 1.f);
    float pooled = g_sums[g * HC + lane] / cnt;
    float p0 = pooled * Wfc[lane];
    float p1 = pooled * Wfc[HC + lane];
#pragma unroll
    for (int off = 16; off; off >>= 1) {
        p0 += __shfl_xor_sync(0xffffffffu, p0, off);
        p1 += __shfl_xor_sync(0xffffffffu, p1, off);
    }
    if (lane == 0) {
        float l0 = p0 + bfc[0];
        float l1 = p1 + bfc[1];
        float mx = fmaxf(l0, l1);
        float lse = mx + logf(expf(l0 - mx) + expf(l1 - mx));
        out[g * 2 + 0] = l0 - lse;
        out[g * 2 + 1] = l1 - lse;
    }
}

// ---------------- launch ----------------
extern "C" void kernel_launch(void* const* d_in, const int* in_sizes, int n_in,
                              void* d_out, int out_size) {
    const int*   ei        = (const int*)  d_in[0];
    const int*   batch     = (const int*)  d_in[1];
    const float* rand_feat = (const float*)d_in[2];
    const float* W1l  = (const float*)d_in[3];
    const float* b1l  = (const float*)d_in[4];
    const float* W1r  = (const float*)d_in[5];
    const float* b1r  = (const float*)d_in[6];
    const float* att1 = (const float*)d_in[7];
    const float* bias1= (const float*)d_in[8];
    const float* W2l  = (const float*)d_in[9];
    const float* b2l  = (const float*)d_in[10];
    const float* W2r  = (const float*)d_in[11];
    const float* b2r  = (const float*)d_in[12];
    const float* att2 = (const float*)d_in[13];
    const float* bias2= (const float*)d_in[14];
    const float* Wfc  = (const float*)d_in[15];
    const float* bfc  = (const float*)d_in[16];
    float* out = (float*)d_out;

    zero_kernel   <<<(N_NODES + 255) / 256, 256>>>();
    degree_kernel <<<(E_EDGES / 4 + 255) / 256, 256>>>(ei);
    scan_kernel   <<<1, 1024>>>();
    scatter_kernel<<<(E_EDGES / 4 + 255) / 256, 256>>>(ei);

    feat_lin1_kernel<<<(N_NODES * HC + 255) / 256, 256>>>(rand_feat, W1l, b1l, W1r, b1r);

    // conv1 + fused lin2
    conv_kernel<0><<<(N_NODES * HC + 255) / 256, 256>>>(
        att1, bias1, W2l, b2l, W2r, b2r, nullptr);
    // conv2 + fused pool
    conv_kernel<1><<<(N_NODES * HC + 255) / 256, 256>>>(
        att2, bias2, nullptr, nullptr, nullptr, nullptr, batch);

    head_kernel<<<G_GRAPHS, 32>>>(batch, Wfc, bfc, out);
}

// round 4
// speedup vs baseline: 1.2613x; 1.0759x over previous
#include <cuda_runtime.h>
#include <math.h>

#define N_NODES 50000
#define E_EDGES 1600000
#define HC      32
#define G_GRAPHS 512

// ---------------- static scratch ----------------
__device__ int   g_outdeg[N_NODES];
__device__ int   g_indeg [N_NODES];
__device__ int   g_rowptr[N_NODES + 1];
__device__ int   g_woff  [N_NODES];
__device__ int   g_col   [E_EDGES];
__device__ float g_xl [N_NODES * HC];
__device__ float g_xr [N_NODES * HC];
__device__ float g_xl2[N_NODES * HC];
__device__ float g_xr2[N_NODES * HC];
__device__ float g_sums[G_GRAPHS * HC];

// ---------------- kernels ----------------
__global__ void zero_kernel() {
    int i = blockIdx.x * blockDim.x + threadIdx.x;
    if (i < N_NODES) { g_outdeg[i] = 0; g_indeg[i] = 0; }
    if (i < G_GRAPHS * HC) g_sums[i] = 0.f;
}

// indeg only (outdeg folded into scatter); 4 edges/thread
__global__ void degree_kernel(const int* __restrict__ ei) {
    int e0 = (blockIdx.x * blockDim.x + threadIdx.x) * 4;
    if (e0 >= E_EDGES) return;
    int4 d = *(const int4*)(ei + E_EDGES + e0);
    atomicAdd(&g_indeg[d.x], 1);  atomicAdd(&g_indeg[d.y], 1);
    atomicAdd(&g_indeg[d.z], 1);  atomicAdd(&g_indeg[d.w], 1);
}

// exclusive scan of indeg -> rowptr (and primes woff). Single 1024-thread block.
__global__ void scan_kernel() {
    __shared__ int part[1024];
    const int t = threadIdx.x;
    const int per = (N_NODES + 1023) / 1024;
    int lo = t * per;
    int hi = min(lo + per, N_NODES);
    int s = 0;
    for (int i = lo; i < hi; i++) s += g_indeg[i];
    part[t] = s;
    __syncthreads();
    for (int off = 1; off < 1024; off <<= 1) {
        int v = (t >= off) ? part[t - off] : 0;
        __syncthreads();
        part[t] += v;
        __syncthreads();
    }
    int run = part[t] - s;
    for (int i = lo; i < hi; i++) {
        g_rowptr[i] = run;
        g_woff[i]   = run;
        run += g_indeg[i];
    }
    if (t == 1023) g_rowptr[N_NODES] = part[1023];
}

// CSR scatter + outdeg accumulation; 4 edges/thread
__global__ void scatter_kernel(const int* __restrict__ ei) {
    int e0 = (blockIdx.x * blockDim.x + threadIdx.x) * 4;
    if (e0 >= E_EDGES) return;
    int4 s = *(const int4*)(ei + e0);
    int4 d = *(const int4*)(ei + E_EDGES + e0);
    int p0 = atomicAdd(&g_woff[d.x], 1);
    int p1 = atomicAdd(&g_woff[d.y], 1);
    int p2 = atomicAdd(&g_woff[d.z], 1);
    int p3 = atomicAdd(&g_woff[d.w], 1);
    g_col[p0] = s.x; g_col[p1] = s.y; g_col[p2] = s.z; g_col[p3] = s.w;
    atomicAdd(&g_outdeg[s.x], 1); atomicAdd(&g_outdeg[s.y], 1);
    atomicAdd(&g_outdeg[s.z], 1); atomicAdd(&g_outdeg[s.w], 1);
}

// x0 = [1, deg, rand]; xl/xr = x0 @ W^T + b. warp per node, lane = out channel
__global__ void feat_lin1_kernel(const float* __restrict__ rand_feat,
                                 const float* __restrict__ Wl, const float* __restrict__ bl,
                                 const float* __restrict__ Wr, const float* __restrict__ br) {
    int idx = blockIdx.x * blockDim.x + threadIdx.x;
    int node = idx >> 5, lane = idx & 31;
    if (node >= N_NODES) return;
    float x1 = (float)(g_outdeg[node] + g_indeg[node]);
    float x2 = rand_feat[node];
    g_xl[idx] = Wl[lane * 3 + 0] + Wl[lane * 3 + 1] * x1 + Wl[lane * 3 + 2] * x2 + bl[lane];
    g_xr[idx] = Wr[lane * 3 + 0] + Wr[lane * 3 + 1] * x1 + Wr[lane * 3 + 2] * x2 + br[lane];
}

// GATv2 conv: warp per destination node, 4 edge-subgroups of 8 lanes,
// each lane holds 4 channels (float4). head = q>>2 where q = lane&7.
// Per-head score reduce = shfl xor 1,2 (stays within head). Cross-subgroup
// accumulator combine = shfl xor 8,16 (q invariant -> head-safe).
// Softmax baseline = self-loop score (exact up to rounding).
// MODE 0: reads g_xl/g_xr, epilogue = fused 32->32 x2 linear -> g_xl2/g_xr2.
// MODE 1: reads g_xl2/g_xr2, epilogue = fused mean-pool atomicAdd into g_sums.
template<int MODE>
__global__ void conv_kernel(const float* __restrict__ att, const float* __restrict__ bias,
                            const float* __restrict__ Wl, const float* __restrict__ bl,
                            const float* __restrict__ Wr, const float* __restrict__ br,
                            const int* __restrict__ batch) {
    const float* __restrict__ xl = (MODE == 0) ? g_xl : g_xl2;
    const float* __restrict__ xr = (MODE == 0) ? g_xr : g_xr2;

    __shared__ float sWl[32 * 33];
    __shared__ float sWr[32 * 33];
    if (MODE == 0) {
        for (int i = threadIdx.x; i < 1024; i += blockDim.x) {
            int r = i >> 5, c = i & 31;
            sWl[r * 33 + c] = Wl[i];
            sWr[r * 33 + c] = Wr[i];
        }
        __syncthreads();
    }
    int gidx = blockIdx.x * blockDim.x + threadIdx.x;
    int node = gidx >> 5, lane = gidx & 31;
    if (node >= N_NODES) return;
    const int sub = lane >> 3;     // edge slot 0..3
    const int q   = lane & 7;      // channel quad 0..7 (channels q*4..q*4+3)
    const unsigned FULL = 0xffffffffu;

    const float4 att4 = *(const float4*)(att + q * 4);
    const float4 xr4  = *(const float4*)(xr + node * HC + q * 4);

    // self-loop term + softmax baseline pself (per head)
    const float4 vs4 = *(const float4*)(xl + node * HC + q * 4);
    float mx = vs4.x + xr4.x, my = vs4.y + xr4.y, mz = vs4.z + xr4.z, mw = vs4.w + xr4.w;
    float ps = fmaxf(mx, 0.2f * mx) * att4.x + fmaxf(my, 0.2f * my) * att4.y
             + fmaxf(mz, 0.2f * mz) * att4.z + fmaxf(mw, 0.2f * mw) * att4.w;
    ps += __shfl_xor_sync(FULL, ps, 1);
    ps += __shfl_xor_sync(FULL, ps, 2);
    const float pself = ps;

    float wself = (sub == 0) ? 1.f : 0.f;
    float denom = wself;
    float4 acc = make_float4(vs4.x * wself, vs4.y * wself, vs4.z * wself, vs4.w * wself);

    const int beg = g_rowptr[node];
    const int end = g_rowptr[node + 1];

    for (int e = beg; e < end; e += 8) {
        int i0 = e + sub;
        int i1 = e + 4 + sub;
        bool ok0 = i0 < end;
        bool ok1 = i1 < end;
        int s0 = ok0 ? __ldg(g_col + i0) : node;
        int s1 = ok1 ? __ldg(g_col + i1) : node;
        float4 a0 = *(const float4*)(xl + s0 * HC + q * 4);
        float4 a1 = *(const float4*)(xl + s1 * HC + q * 4);

        // edge group 0
        {
            float m0 = a0.x + xr4.x, m1 = a0.y + xr4.y, m2 = a0.z + xr4.z, m3 = a0.w + xr4.w;
            float p = fmaxf(m0, 0.2f * m0) * att4.x + fmaxf(m1, 0.2f * m1) * att4.y
                    + fmaxf(m2, 0.2f * m2) * att4.z + fmaxf(m3, 0.2f * m3) * att4.w;
            p += __shfl_xor_sync(FULL, p, 1);
            p += __shfl_xor_sync(FULL, p, 2);
            float w = ok0 ? __expf(p - pself) : 0.f;
            denom += w;
            acc.x = fmaf(w, a0.x, acc.x);
            acc.y = fmaf(w, a0.y, acc.y);
            acc.z = fmaf(w, a0.z, acc.z);
            acc.w = fmaf(w, a0.w, acc.w);
        }
        // edge group 1
        {
            float m0 = a1.x + xr4.x, m1 = a1.y + xr4.y, m2 = a1.z + xr4.z, m3 = a1.w + xr4.w;
            float p = fmaxf(m0, 0.2f * m0) * att4.x + fmaxf(m1, 0.2f * m1) * att4.y
                    + fmaxf(m2, 0.2f * m2) * att4.z + fmaxf(m3, 0.2f * m3) * att4.w;
            p += __shfl_xor_sync(FULL, p, 1);
            p += __shfl_xor_sync(FULL, p, 2);
            float w = ok1 ? __expf(p - pself) : 0.f;
            denom += w;
            acc.x = fmaf(w, a1.x, acc.x);
            acc.y = fmaf(w, a1.y, acc.y);
            acc.z = fmaf(w, a1.z, acc.z);
            acc.w = fmaf(w, a1.w, acc.w);
        }
    }

    // combine the 4 edge subgroups (q invariant -> per-head denom stays correct)
#pragma unroll
    for (int off = 8; off <= 16; off <<= 1) {
        acc.x += __shfl_xor_sync(FULL, acc.x, off);
        acc.y += __shfl_xor_sync(FULL, acc.y, off);
        acc.z += __shfl_xor_sync(FULL, acc.z, off);
        acc.w += __shfl_xor_sync(FULL, acc.w, off);
        denom += __shfl_xor_sync(FULL, denom, off);
    }

    const float4 b4 = *(const float4*)(bias + q * 4);
    float rd = __fdividef(1.f, denom + 1e-16f);
    float4 o4;
    o4.x = fmaf(acc.x, rd, b4.x);
    o4.y = fmaf(acc.y, rd, b4.y);
    o4.z = fmaf(acc.z, rd, b4.z);
    o4.w = fmaf(acc.w, rd, b4.w);
    // ELU
    o4.x = o4.x > 0.f ? o4.x : (__expf(o4.x) - 1.f);
    o4.y = o4.y > 0.f ? o4.y : (__expf(o4.y) - 1.f);
    o4.z = o4.z > 0.f ? o4.z : (__expf(o4.z) - 1.f);
    o4.w = o4.w > 0.f ? o4.w : (__expf(o4.w) - 1.f);

    if (MODE == 0) {
        // fused lin2 via shuffle broadcast: o_k lives in lane k>>2, component k&3
        float aL = bl[lane], aR = br[lane];
#pragma unroll
        for (int k = 0; k < 32; k++) {
            float comp = (k & 3) == 0 ? o4.x : (k & 3) == 1 ? o4.y : (k & 3) == 2 ? o4.z : o4.w;
            float hk = __shfl_sync(FULL, comp, k >> 2);
            aL = fmaf(hk, sWl[lane * 33 + k], aL);
            aR = fmaf(hk, sWr[lane * 33 + k], aR);
        }
        g_xl2[node * HC + lane] = aL;
        g_xr2[node * HC + lane] = aR;
    } else {
        if (sub == 0) {
            int g = batch[node];
            float* dst = &g_sums[g * HC + q * 4];
            atomicAdd(dst + 0, o4.x);
            atomicAdd(dst + 1, o4.y);
            atomicAdd(dst + 2, o4.z);
            atomicAdd(dst + 3, o4.w);
        }
    }
}

__device__ __forceinline__ int lbound(const int* __restrict__ a, int key) {
    int lo = 0, hi = N_NODES;
    while (lo < hi) {
        int mid = (lo + hi) >> 1;
        if (a[mid] < key) lo = mid + 1; else hi = mid;
    }
    return lo;
}

// one warp per graph: counts via binary search on sorted batch, mean pool, fc, log_softmax
__global__ void head_kernel(const int* __restrict__ batch,
                            const float* __restrict__ Wfc, const float* __restrict__ bfc,
                            float* __restrict__ out) {
    int g = blockIdx.x;
    int lane = threadIdx.x;
    int lo = lbound(batch, g);
    int hi = lbound(batch, g + 1);
    float cnt = fmaxf((float)(hi - lo), 1.f);
    float pooled = g_sums[g * HC + lane] / cnt;
    float p0 = pooled * Wfc[lane];
    float p1 = pooled * Wfc[HC + lane];
#pragma unroll
    for (int off = 16; off; off >>= 1) {
        p0 += __shfl_xor_sync(0xffffffffu, p0, off);
        p1 += __shfl_xor_sync(0xffffffffu, p1, off);
    }
    if (lane == 0) {
        float l0 = p0 + bfc[0];
        float l1 = p1 + bfc[1];
        float mx = fmaxf(l0, l1);
        float lse = mx + logf(expf(l0 - mx) + expf(l1 - mx));
        out[g * 2 + 0] = l0 - lse;
        out[g * 2 + 1] = l1 - lse;
    }
}

// ---------------- launch ----------------
extern "C" void kernel_launch(void* const* d_in, const int* in_sizes, int n_in,
                              void* d_out, int out_size) {
    const int*   ei        = (const int*)  d_in[0];
    const int*   batch     = (const int*)  d_in[1];
    const float* rand_feat = (const float*)d_in[2];
    const float* W1l  = (const float*)d_in[3];
    const float* b1l  = (const float*)d_in[4];
    const float* W1r  = (const float*)d_in[5];
    const float* b1r  = (const float*)d_in[6];
    const float* att1 = (const float*)d_in[7];
    const float* bias1= (const float*)d_in[8];
    const float* W2l  = (const float*)d_in[9];
    const float* b2l  = (const float*)d_in[10];
    const float* W2r  = (const float*)d_in[11];
    const float* b2r  = (const float*)d_in[12];
    const float* att2 = (const float*)d_in[13];
    const float* bias2= (const float*)d_in[14];
    const float* Wfc  = (const float*)d_in[15];
    const float* bfc  = (const float*)d_in[16];
    float* out = (float*)d_out;

    zero_kernel   <<<(N_NODES + 255) / 256, 256>>>();
    degree_kernel <<<(E_EDGES / 4 + 255) / 256, 256>>>(ei);
    scan_kernel   <<<1, 1024>>>();
    scatter_kernel<<<(E_EDGES / 4 + 255) / 256, 256>>>(ei);

    feat_lin1_kernel<<<(N_NODES * HC + 255) / 256, 256>>>(rand_feat, W1l, b1l, W1r, b1r);

    conv_kernel<0><<<(N_NODES * HC + 255) / 256, 256>>>(
        att1, bias1, W2l, b2l, W2r, b2r, nullptr);
    conv_kernel<1><<<(N_NODES * HC + 255) / 256, 256>>>(
        att2, bias2, nullptr, nullptr, nullptr, nullptr, batch);

    head_kernel<<<G_GRAPHS, 32>>>(batch, Wfc, bfc, out);
}